// round 15
// baseline (speedup 1.0000x reference)
#include <cuda_runtime.h>
#include <cuda_bf16.h>
#include <math.h>

// Rigid-warp + trilinear resample of a 256^3 fp32 volume — single direct pass.
// Setup kernel computes T = inv(flo_v2r) @ T_rig @ ref_v2r -> g_T plus corner
// bounds for a 6-compare interior test.
// Main kernel: 2x2 (i,j) outputs per thread at fixed k, __launch_bounds__(256,8)
// to force regs<=32 (occupancy was the binding constraint at regs=40).
// Interior path consumes loads early (z-lerp immediately) to fit the register
// budget; reuse chains B<-A, C<-A, D<-C kept as predicated selects.
// Boundary path is a compact unroll-1 loop (one Tap live at a time).
// All fp32.

#define DIMD 256
#define DIMH 256
#define DIMW 256

__device__ float g_T[18];   // [0..11] transform rows, [12..14] lo, [15..17] hi

__device__ __forceinline__ void matmul3(const float a[9], const float b[9], float c[9]) {
    #pragma unroll
    for (int i = 0; i < 3; i++)
        #pragma unroll
        for (int j = 0; j < 3; j++)
            c[i * 3 + j] = a[i * 3 + 0] * b[0 * 3 + j]
                         + a[i * 3 + 1] * b[1 * 3 + j]
                         + a[i * 3 + 2] * b[2 * 3 + j];
}

__device__ __forceinline__ void matmul4(const float a[16], const float b[16], float c[16]) {
    #pragma unroll
    for (int i = 0; i < 4; i++)
        #pragma unroll
        for (int j = 0; j < 4; j++)
            c[i * 4 + j] = a[i * 4 + 0] * b[0 * 4 + j]
                         + a[i * 4 + 1] * b[1 * 4 + j]
                         + a[i * 4 + 2] * b[2 * 4 + j]
                         + a[i * 4 + 3] * b[3 * 4 + j];
}

__device__ void inv4(const float m[16], float invOut[16]) {
    float inv[16];
    inv[0]  =  m[5]*m[10]*m[15] - m[5]*m[11]*m[14] - m[9]*m[6]*m[15] +
               m[9]*m[7]*m[14]  + m[13]*m[6]*m[11] - m[13]*m[7]*m[10];
    inv[4]  = -m[4]*m[10]*m[15] + m[4]*m[11]*m[14] + m[8]*m[6]*m[15] -
               m[8]*m[7]*m[14]  - m[12]*m[6]*m[11] + m[12]*m[7]*m[10];
    inv[8]  =  m[4]*m[9]*m[15]  - m[4]*m[11]*m[13] - m[8]*m[5]*m[15] +
               m[8]*m[7]*m[13]  + m[12]*m[5]*m[11] - m[12]*m[7]*m[9];
    inv[12] = -m[4]*m[9]*m[14]  + m[4]*m[10]*m[13] + m[8]*m[5]*m[14] -
               m[8]*m[6]*m[13]  - m[12]*m[5]*m[10] + m[12]*m[6]*m[9];
    inv[1]  = -m[1]*m[10]*m[15] + m[1]*m[11]*m[14] + m[9]*m[2]*m[15] -
               m[9]*m[3]*m[14]  - m[13]*m[2]*m[11] + m[13]*m[3]*m[10];
    inv[5]  =  m[0]*m[10]*m[15] - m[0]*m[11]*m[14] - m[8]*m[2]*m[15] +
               m[8]*m[3]*m[14]  + m[12]*m[2]*m[11] - m[12]*m[3]*m[10];
    inv[9]  = -m[0]*m[9]*m[15]  + m[0]*m[11]*m[13] + m[8]*m[1]*m[15] -
               m[8]*m[3]*m[13]  - m[12]*m[1]*m[11] + m[12]*m[3]*m[9];
    inv[13] =  m[0]*m[9]*m[14]  - m[0]*m[10]*m[13] - m[8]*m[1]*m[14] +
               m[8]*m[2]*m[13]  + m[12]*m[1]*m[10] - m[12]*m[2]*m[9];
    inv[2]  =  m[1]*m[6]*m[15]  - m[1]*m[7]*m[14]  - m[5]*m[2]*m[15] +
               m[5]*m[3]*m[14]  + m[13]*m[2]*m[7]  - m[13]*m[3]*m[6];
    inv[6]  = -m[0]*m[6]*m[15]  + m[0]*m[7]*m[14]  + m[4]*m[2]*m[15] -
               m[4]*m[3]*m[14]  - m[12]*m[2]*m[7]  + m[12]*m[3]*m[6];
    inv[10] =  m[0]*m[5]*m[15]  - m[0]*m[7]*m[13]  - m[4]*m[1]*m[15] +
               m[4]*m[3]*m[13]  + m[12]*m[1]*m[7]  - m[12]*m[3]*m[5];
    inv[14] = -m[0]*m[5]*m[14]  + m[0]*m[6]*m[13]  + m[4]*m[1]*m[14] -
               m[4]*m[2]*m[13]  - m[12]*m[1]*m[6]  + m[12]*m[2]*m[5];
    inv[3]  = -m[1]*m[6]*m[11]  + m[1]*m[7]*m[10]  + m[5]*m[2]*m[11] -
               m[5]*m[3]*m[10]  - m[9]*m[2]*m[7]   + m[9]*m[3]*m[6];
    inv[7]  =  m[0]*m[6]*m[11]  - m[0]*m[7]*m[10]  - m[4]*m[2]*m[11] +
               m[4]*m[3]*m[10]  + m[8]*m[2]*m[7]   - m[8]*m[3]*m[6];
    inv[11] = -m[0]*m[5]*m[11]  + m[0]*m[7]*m[9]   + m[4]*m[1]*m[11] -
               m[4]*m[3]*m[9]   - m[8]*m[1]*m[7]   + m[8]*m[3]*m[5];
    inv[15] =  m[0]*m[5]*m[10]  - m[0]*m[6]*m[9]   - m[4]*m[1]*m[10] +
               m[4]*m[2]*m[9]   + m[8]*m[1]*m[6]   - m[8]*m[2]*m[5];

    float det = m[0]*inv[0] + m[1]*inv[4] + m[2]*inv[8] + m[3]*inv[12];
    det = 1.0f / det;
    #pragma unroll
    for (int i = 0; i < 16; i++) invOut[i] = inv[i] * det;
}

__global__ void setup_T_kernel(const float* __restrict__ rot,
                               const float* __restrict__ tra,
                               const float* __restrict__ ref_v2r,
                               const float* __restrict__ flo_v2r) {
    if (threadIdx.x != 0) return;
    float cx = cosf(rot[0]), cy = cosf(rot[1]), cz = cosf(rot[2]);
    float sx = sinf(rot[0]), sy = sinf(rot[1]), sz = sinf(rot[2]);

    float Rx[9] = {1, 0, 0,  0, cx, -sx,  0, sx, cx};
    float Ry[9] = {cy, 0, sy,  0, 1, 0,  -sy, 0, cy};
    float Rz[9] = {cz, -sz, 0,  sz, cz, 0,  0, 0, 1};
    float RxRy[9], R[9];
    matmul3(Rx, Ry, RxRy);
    matmul3(RxRy, Rz, R);

    float Trig[16] = {
        R[0], R[1], R[2], tra[0],
        R[3], R[4], R[5], tra[1],
        R[6], R[7], R[8], tra[2],
        0.f,  0.f,  0.f,  1.f
    };

    float ref[16], flo[16];
    #pragma unroll
    for (int i = 0; i < 16; i++) { ref[i] = ref_v2r[i]; flo[i] = flo_v2r[i]; }

    float flo_inv[16], A[16], T[16];
    inv4(flo, flo_inv);
    matmul4(Trig, ref, A);
    matmul4(flo_inv, A, T);

    #pragma unroll
    for (int i = 0; i < 12; i++) g_T[i] = T[i];

    #pragma unroll
    for (int c = 0; c < 3; c++) {
        const float t0 = T[c * 4 + 0];        // delta for i+1
        const float t1 = T[c * 4 + 1];        // delta for j+1
        g_T[12 + c] = fminf(fminf(0.f, t0), fminf(t1, t0 + t1));
        g_T[15 + c] = fmaxf(fmaxf(0.f, t0), fmaxf(t1, t0 + t1));
    }
}

__device__ __forceinline__ float lerpf(float a, float b, float w) {
    return fmaf(w, b - a, a);
}

__global__ void __launch_bounds__(256, 8)
warp_trilinear_direct4_kernel(const float* __restrict__ X, float* __restrict__ out) {
    const int k  = threadIdx.x;              // W (stride-1)
    const int jA = (blockIdx.x & 127) << 1;  // even j
    const int iA = (blockIdx.x >> 7) << 1;   // even i

    const float T00 = g_T[0], T01 = g_T[1], T02 = g_T[2],  T03 = g_T[3];
    const float T10 = g_T[4], T11 = g_T[5], T12 = g_T[6],  T13 = g_T[7];
    const float T20 = g_T[8], T21 = g_T[9], T22 = g_T[10], T23 = g_T[11];

    const float fi = (float)iA, fj = (float)jA, fk = (float)k;
    const float diA = fmaf(T00, fi, fmaf(T01, fj, fmaf(T02, fk, T03)));
    const float djA = fmaf(T10, fi, fmaf(T11, fj, fmaf(T12, fk, T13)));
    const float dkA = fmaf(T20, fi, fmaf(T21, fj, fmaf(T22, fk, T23)));

    const int idxA = (iA << 16) | (jA << 8) | k;

    // Interior test via precomputed corner bounds: 6 compares.
    const bool interior =
        (diA + g_T[12] > 0.f) & (diA + g_T[15] < 255.f) &
        (djA + g_T[13] > 0.f) & (djA + g_T[16] < 255.f) &
        (dkA + g_T[14] > 0.f) & (dkA + g_T[17] < 255.f);

    if (interior) {
        // ---------- FAST interior path (register-lean ordering) ----------
        // A tap
        const float fxA = floorf(diA), fyA = floorf(djA), fzA = floorf(dkA);
        const float wxA = diA - fxA, wyA = djA - fyA, wzA = dkA - fzA;
        const int bA = ((int)fxA << 16) | ((int)fyA << 8) | (int)fzA;

        // A raw loads (kept live for B/C reuse)
        const float a000 = __ldg(X + bA);
        const float a001 = __ldg(X + bA + 1);
        const float a010 = __ldg(X + bA + 256);
        const float a011 = __ldg(X + bA + 257);
        const float a100 = __ldg(X + bA + 65536);
        const float a101 = __ldg(X + bA + 65537);
        const float a110 = __ldg(X + bA + 65792);
        const float a111 = __ldg(X + bA + 65793);

        // ---- B (i, j+1): reuse A's y1 planes; consume immediately ----
        {
            const float di = diA + T01, dj = djA + T11, dk = dkA + T21;
            const float fx = floorf(di), fy = floorf(dj), fz = floorf(dk);
            const float wx = di - fx, wy = dj - fy, wz = dk - fz;
            const int b = ((int)fx << 16) | ((int)fy << 8) | (int)fz;
            const bool m = (b == bA + 256);
            const float v000 = m ? a010 : __ldg(X + b);
            const float v001 = m ? a011 : __ldg(X + b + 1);
            const float v100 = m ? a110 : __ldg(X + b + 65536);
            const float v101 = m ? a111 : __ldg(X + b + 65537);
            const float v010 = __ldg(X + b + 256);
            const float v011 = __ldg(X + b + 257);
            const float v110 = __ldg(X + b + 65792);
            const float v111 = __ldg(X + b + 65793);
            const float c00 = lerpf(v000, v001, wz);
            const float c01 = lerpf(v010, v011, wz);
            const float c10 = lerpf(v100, v101, wz);
            const float c11 = lerpf(v110, v111, wz);
            out[idxA + 256] = lerpf(lerpf(c00, c01, wy), lerpf(c10, c11, wy), wx);
        }

        // ---- C (i+1, j): reuse A's x1 planes; raw kept live for D ----
        const float diC = diA + T00, djC = djA + T10, dkC = dkA + T20;
        const float fxC = floorf(diC), fyC = floorf(djC), fzC = floorf(dkC);
        const float wxC = diC - fxC, wyC = djC - fyC, wzC = dkC - fzC;
        const int bC = ((int)fxC << 16) | ((int)fyC << 8) | (int)fzC;
        const bool mC = (bC == bA + 65536);
        const float c000 = mC ? a100 : __ldg(X + bC);
        const float c001 = mC ? a101 : __ldg(X + bC + 1);
        const float c010 = mC ? a110 : __ldg(X + bC + 256);
        const float c011 = mC ? a111 : __ldg(X + bC + 257);
        const float c100 = __ldg(X + bC + 65536);
        const float c101 = __ldg(X + bC + 65537);
        const float c110 = __ldg(X + bC + 65792);
        const float c111 = __ldg(X + bC + 65793);

        // ---- A interpolate + store (A raw dies here) ----
        {
            const float c00 = lerpf(a000, a001, wzA);
            const float c01 = lerpf(a010, a011, wzA);
            const float c10 = lerpf(a100, a101, wzA);
            const float c11 = lerpf(a110, a111, wzA);
            out[idxA] = lerpf(lerpf(c00, c01, wyA), lerpf(c10, c11, wyA), wxA);
        }

        // ---- D (i+1, j+1): reuse C's y1 planes; consume immediately ----
        {
            const float di = diC + T01, dj = djC + T11, dk = dkC + T21;
            const float fx = floorf(di), fy = floorf(dj), fz = floorf(dk);
            const float wx = di - fx, wy = dj - fy, wz = dk - fz;
            const int b = ((int)fx << 16) | ((int)fy << 8) | (int)fz;
            const bool m = (b == bC + 256);
            const float v000 = m ? c010 : __ldg(X + b);
            const float v001 = m ? c011 : __ldg(X + b + 1);
            const float v100 = m ? c110 : __ldg(X + b + 65536);
            const float v101 = m ? c111 : __ldg(X + b + 65537);
            const float v010 = __ldg(X + b + 256);
            const float v011 = __ldg(X + b + 257);
            const float v110 = __ldg(X + b + 65792);
            const float v111 = __ldg(X + b + 65793);
            const float c00 = lerpf(v000, v001, wz);
            const float c01 = lerpf(v010, v011, wz);
            const float c10 = lerpf(v100, v101, wz);
            const float c11 = lerpf(v110, v111, wz);
            out[idxA + 65536 + 256] =
                lerpf(lerpf(c00, c01, wy), lerpf(c10, c11, wy), wx);
        }

        // ---- C interpolate + store ----
        {
            const float c00 = lerpf(c000, c001, wzC);
            const float c01 = lerpf(c010, c011, wzC);
            const float c10 = lerpf(c100, c101, wzC);
            const float c11 = lerpf(c110, c111, wzC);
            out[idxA + 65536] =
                lerpf(lerpf(c00, c01, wyC), lerpf(c10, c11, wyC), wxC);
        }
    } else {
        // ---------- general boundary path: compact loop, one tap live ----------
        #pragma unroll 1
        for (int t = 0; t < 4; t++) {
            const float oi = (t & 2) ? T00 : 0.f;
            const float oj = (t & 2) ? T10 : 0.f;
            const float ok_ = (t & 2) ? T20 : 0.f;
            const float di = diA + oi + ((t & 1) ? T01 : 0.f);
            const float dj = djA + oj + ((t & 1) ? T11 : 0.f);
            const float dk = dkA + ok_ + ((t & 1) ? T21 : 0.f);

            const float MX = 255.f;
            const bool ok = (di > 0.f) & (dj > 0.f) & (dk > 0.f) &
                            (di <= MX) & (dj <= MX) & (dk <= MX);
            const float fx = floorf(di), fy = floorf(dj), fz = floorf(dk);
            const float wx = di - fx, wy = dj - fy, wz = dk - fz;
            const int x0 = (int)fminf(fmaxf(fx, 0.f), MX);
            const int y0 = (int)fminf(fmaxf(fy, 0.f), MX);
            const int z0 = (int)fminf(fmaxf(fz, 0.f), MX);
            const int b = (x0 << 16) | (y0 << 8) | z0;
            const int dx = (x0 < 255) ? 65536 : 0;
            const int dy = (y0 < 255) ? 256 : 0;
            const int dz = (z0 < 255) ? 1 : 0;

            const float v000 = __ldg(X + b);
            const float v001 = __ldg(X + b + dz);
            const float v010 = __ldg(X + b + dy);
            const float v011 = __ldg(X + b + dy + dz);
            const float v100 = __ldg(X + b + dx);
            const float v101 = __ldg(X + b + dx + dz);
            const float v110 = __ldg(X + b + dx + dy);
            const float v111 = __ldg(X + b + dx + dy + dz);

            const float c00 = lerpf(v000, v001, wz);
            const float c01 = lerpf(v010, v011, wz);
            const float c10 = lerpf(v100, v101, wz);
            const float c11 = lerpf(v110, v111, wz);
            const float v = lerpf(lerpf(c00, c01, wy), lerpf(c10, c11, wy), wx);

            const int off = ((t & 2) ? 65536 : 0) + ((t & 1) ? 256 : 0);
            out[idxA + off] = ok ? v : 0.f;
        }
    }
}

extern "C" void kernel_launch(void* const* d_in, const int* in_sizes, int n_in,
                              void* d_out, int out_size) {
    const float* image = (const float*)d_in[0];
    const float* rot   = (const float*)d_in[1];
    const float* tra   = (const float*)d_in[2];
    const float* refm  = (const float*)d_in[3];
    const float* flom  = (const float*)d_in[4];
    float* out = (float*)d_out;

    setup_T_kernel<<<1, 32>>>(rot, tra, refm, flom);
    warp_trilinear_direct4_kernel<<<(DIMD / 2) * (DIMH / 2), DIMW>>>(image, out);
}